// round 7
// baseline (speedup 1.0000x reference)
#include <cuda_runtime.h>
#include <math.h>

#define N_PTS   524288
#define FD      8
#define NUM     128
#define MAXIT   5
#define EPSF    1e-6f
#define THRESH2 1e-8f        /* (1e-4)^2 */
#define NBLK    (N_PTS / 256)   /* 2048 */
#define TPB_SEG 256
#define TILE    768             /* 2*768*8*4 = 49152 B static smem (max) */

// ---- device scratch (no allocations allowed) ----
__device__ float  g_centers[NUM * FD];
__device__ int    g_counts[NUM];
__device__ float  g_dsq[NUM];
__device__ int    g_labels[N_PTS];
__device__ int    g_converged;
__device__ int    g_ticket1;
__device__ int    g_ticket2;
__device__ __align__(16) float2 g_xy[N_PTS];  // packed first-2 coords (4 MB)
// counting-sort scratch
__device__ int    g_blockhist[NBLK * NUM];
__device__ int    g_blockpre[NBLK * NUM];
__device__ int    g_base[NUM];
__device__ int    g_total[NUM];
__device__ int    g_idx[N_PTS];

// ------------------------------------------------------------------
__global__ void initKernel(const float* __restrict__ centers_in) {
    int t = threadIdx.x;                    // 1024 threads, 1 block
    g_centers[t] = centers_in[t];           // NUM*FD == 1024
    if (t < NUM) g_counts[t] = 0;
    if (t == 0) { g_converged = 0; g_ticket1 = 0; g_ticket2 = 0; }
}

// Pack xy coords once (coords never change).
__global__ void __launch_bounds__(256) packKernel(const float* __restrict__ data) {
    int idx = blockIdx.x * 256 + threadIdx.x;
    g_xy[idx] = *(const float2*)(data + (size_t)idx * FD);
}

// ------------------------------------------------------------------
// Iteration-0 in-radius counts (initial centers). Exact replication of
// in_r = sqrt_rn(dx*dx+dy*dy) <= r via sp2 <= Y0.
__global__ void __launch_bounds__(256) countKernel(float Y0) {
    __shared__ float2 c2[NUM];
    __shared__ int    scnt[NUM];
    int t = threadIdx.x;
    if (t < NUM) {
        c2[t] = make_float2(g_centers[t * FD], g_centers[t * FD + 1]);
        scnt[t] = 0;
    }
    __syncthreads();

    int idx  = blockIdx.x * 256 + t;
    float2 p = g_xy[idx];
    int lane = t & 31;

    int cnt0 = 0, cnt1 = 0, cnt2 = 0, cnt3 = 0;
    #pragma unroll 4
    for (int ii = 0; ii < 32; ii++) {
        bool mine = (lane == ii);
        #pragma unroll
        for (int q = 0; q < 4; q++) {
            int i = q * 32 + ii;
            float dx = p.x - c2[i].x;
            float dy = p.y - c2[i].y;
            float sp2 = __fadd_rn(__fmul_rn(dx, dx), __fmul_rn(dy, dy));
            unsigned m = __ballot_sync(0xffffffffu, sp2 <= Y0);
            int pc = __popc(m);
            if (mine) {
                if (q == 0) cnt0 += pc;
                if (q == 1) cnt1 += pc;
                if (q == 2) cnt2 += pc;
                if (q == 3) cnt3 += pc;
            }
        }
    }
    atomicAdd(&scnt[lane],      cnt0);
    atomicAdd(&scnt[lane + 32], cnt1);
    atomicAdd(&scnt[lane + 64], cnt2);
    atomicAdd(&scnt[lane + 96], cnt3);
    __syncthreads();
    if (t < NUM) atomicAdd(&g_counts[t], scnt[t]);
}

// ------------------------------------------------------------------
// Assignment: faithful reference fp arithmetic, + per-block label histogram.
__global__ void __launch_bounds__(256) assignKernel(const float* __restrict__ data,
                                                    float Y0) {
    if (g_converged) return;
    __shared__ float4 sc[NUM * 2];
    __shared__ int    shist[NUM];
    int t = threadIdx.x;

    {   // centers with "enough" gate baked into coord 0
        float4 v = ((const float4*)g_centers)[t];
        if ((t & 1) == 0) {
            if (g_counts[t >> 1] <= 1) v.x += 1e9f;
        }
        sc[t] = v;
    }
    if (t < NUM) shist[t] = 0;
    __syncthreads();

    int idx = blockIdx.x * 256 + t;
    float4 p0 = ((const float4*)data)[2 * idx];
    float4 p1 = ((const float4*)data)[2 * idx + 1];

    float dval = 1000.0f;
    int   label = -1;

    for (int i = 0; i < NUM; i++) {
        float4 c0 = sc[2 * i];
        float dx0 = p0.x - c0.x;
        float dx1 = p0.y - c0.y;
        float sp2 = __fadd_rn(__fmul_rn(dx0, dx0), __fmul_rn(dx1, dx1));
        bool need = (sp2 <= Y0) && (dval > 0.0f);
        if (__any_sync(0xffffffffu, need)) {
            float4 c1 = sc[2 * i + 1];
            float t0 = __fadd_rn(dx0, EPSF);
            float t1 = __fadd_rn(dx1, EPSF);
            float t2 = __fadd_rn(p0.z - c0.z, EPSF);
            float t3 = __fadd_rn(p0.w - c0.w, EPSF);
            float t4 = __fadd_rn(p1.x - c1.x, EPSF);
            float t5 = __fadd_rn(p1.y - c1.y, EPSF);
            float t6 = __fadd_rn(p1.z - c1.z, EPSF);
            float t7 = __fadd_rn(p1.w - c1.w, EPSF);
            float s = __fmul_rn(t0, t0);
            s = __fadd_rn(s, __fmul_rn(t1, t1));
            s = __fadd_rn(s, __fmul_rn(t2, t2));
            s = __fadd_rn(s, __fmul_rn(t3, t3));
            s = __fadd_rn(s, __fmul_rn(t4, t4));
            s = __fadd_rn(s, __fmul_rn(t5, t5));
            s = __fadd_rn(s, __fmul_rn(t6, t6));
            s = __fadd_rn(s, __fmul_rn(t7, t7));
            float D = __fsqrt_rn(s);
            if (need) {
                if (D < dval) { label = i; dval = D; }
                else          { dval = 0.0f; }
            }
        } else if (__all_sync(0xffffffffu, dval == 0.0f)) {
            break;   // whole warp poisoned: provable no-op for all lanes
        }
    }

    g_labels[idx] = label;
    if (label >= 0) atomicAdd(&shist[label], 1);
    __syncthreads();
    if (t < NUM) g_blockhist[blockIdx.x * NUM + t] = shist[t];
}

// ------------------------------------------------------------------
// Per-cluster exclusive prefix over the 2048 block histograms, with the
// cross-cluster base scan fused into the last-arriving block (ticket).
__global__ void __launch_bounds__(128) scanKernel() {
    if (g_converged) return;
    __shared__ int wsum[4];
    __shared__ int sh[NUM];
    __shared__ int lastFlag;
    int cl   = blockIdx.x;
    int t    = threadIdx.x;             // 0..127
    int lane = t & 31, wid = t >> 5;
    const int PER = NBLK / 128;         // 16

    int v[PER];
    int s = 0;
    #pragma unroll
    for (int j = 0; j < PER; j++) {
        v[j] = g_blockhist[(t * PER + j) * NUM + cl];
        s += v[j];
    }

    int inc = s;
    #pragma unroll
    for (int o = 1; o < 32; o <<= 1) {
        int x = __shfl_up_sync(0xffffffffu, inc, o);
        if (lane >= o) inc += x;
    }
    if (lane == 31) wsum[wid] = inc;
    __syncthreads();
    int woff = 0;
    #pragma unroll
    for (int w = 0; w < 4; w++)
        if (w < wid) woff += wsum[w];

    if (t == 127) g_total[cl] = woff + inc;

    int run = woff + (inc - s);
    #pragma unroll
    for (int j = 0; j < PER; j++) {
        g_blockpre[(t * PER + j) * NUM + cl] = run;
        run += v[j];
    }

    // ---- fused base scan (last block via ticket) ----
    __threadfence();
    __syncthreads();
    if (t == 0) {
        int old = atomicAdd(&g_ticket1, 1);
        lastFlag = (old == NUM - 1);
    }
    __syncthreads();
    if (lastFlag) {
        int tv = g_total[t];
        sh[t] = tv;
        __syncthreads();
        #pragma unroll
        for (int o = 1; o < NUM; o <<= 1) {
            int x = (t >= o) ? sh[t - o] : 0;
            __syncthreads();
            sh[t] += x;
            __syncthreads();
        }
        g_base[t] = sh[t] - tv;
        if (t == 0) g_ticket1 = 0;
    }
}

// ------------------------------------------------------------------
// Stable scatter: point index -> g_idx, ascending index within each cluster.
__global__ void __launch_bounds__(256) scatterKernel() {
    if (g_converged) return;
    __shared__ int whist[8][NUM];
    int t    = threadIdx.x;
    int wid  = t >> 5;
    int lane = t & 31;

    #pragma unroll
    for (int j = t; j < 8 * NUM; j += 256) ((int*)whist)[j] = 0;
    __syncthreads();

    int idx = blockIdx.x * 256 + t;
    int lab = g_labels[idx];

    unsigned mask = __match_any_sync(0xffffffffu, lab);
    int rank   = __popc(mask & ((1u << lane) - 1u));
    int leader = __ffs(mask) - 1;
    if (lab >= 0 && lane == leader) whist[wid][lab] = __popc(mask);
    __syncthreads();

    if (t < NUM) {
        int run = 0;
        #pragma unroll
        for (int w = 0; w < 8; w++) {
            int v = whist[w][t];
            whist[w][t] = run;
            run += v;
        }
    }
    __syncthreads();

    if (lab >= 0) {
        int pos = g_base[lab] + g_blockpre[blockIdx.x * NUM + lab]
                + whist[wid][lab] + rank;
        g_idx[pos] = idx;
    }
}

// ------------------------------------------------------------------
// Exact ascending-order segment sums (tile-pipelined) FUSED with:
//   - per-cluster center update (identical fp ops/order as before)
//   - next iteration's in-radius count for this cluster's NEW center
//     (hidden in the shadow of the longest chain)
//   - convergence check in the last-arriving block (identical tree order)
__global__ void __launch_bounds__(TPB_SEG) segsumKernel(const float* __restrict__ data,
                                                        float Y0, int doCount) {
    if (g_converged) return;
    __shared__ float buf[2][TILE][FD];     // 49152 B; tail phases reuse it
    int cl = blockIdx.x;
    int t  = threadIdx.x;
    int start = g_base[cl];
    int n     = g_total[cl];
    int ntiles = (n + TILE - 1) / TILE;

    #define LOAD_TILE(g, s)                                              \
        do {                                                             \
            _Pragma("unroll")                                            \
            for (int h = 0; h < TILE / TPB_SEG; h++) {                   \
                int p = (g) * TILE + h * TPB_SEG + t;                    \
                if (p < n) {                                             \
                    int id = g_idx[start + p];                           \
                    float4 a = ((const float4*)data)[2 * id];            \
                    float4 b = ((const float4*)data)[2 * id + 1];        \
                    float* dst = buf[s][h * TPB_SEG + t];                \
                    ((float4*)dst)[0] = a;                               \
                    ((float4*)dst)[1] = b;                               \
                }                                                        \
            }                                                            \
        } while (0)

    if (ntiles > 0) LOAD_TILE(0, 0);
    __syncthreads();

    float acc = 0.0f;
    for (int g = 0; g < ntiles; g++) {
        int s = g & 1;
        if (g + 1 < ntiles) LOAD_TILE(g + 1, s ^ 1);
        int m = min(n - g * TILE, TILE);
        if (t < FD) {
            #pragma unroll 16
            for (int k = 0; k < m; k++)
                acc = __fadd_rn(acc, buf[s][k][t]);
        }
        __syncthreads();
    }
    #undef LOAD_TILE

    // ---- fused center update (fp ops identical to old updateKernel) ----
    float* scr = &buf[0][0][0];
    if (t < FD) {
        float oldc = g_centers[cl * FD + t];
        float cntf = (float)n;
        float den  = fmaxf(cntf, 1.0f);
        float mval = __fdiv_rn(acc, den);
        float nc   = (cntf > 0.0f) ? mval : oldc;
        float d    = nc - oldc;
        g_centers[cl * FD + t] = nc;
        scr[t]     = d;
        scr[8 + t] = nc;        // dims 0,1 used as new cc below
    }
    __syncthreads();
    if (t == 0) {
        float dsq = 0.0f;
        #pragma unroll
        for (int k = 0; k < FD; k++)
            dsq = __fadd_rn(dsq, __fmul_rn(scr[k], scr[k]));
        g_dsq[cl] = dsq;
    }
    float ccx = scr[8], ccy = scr[9];
    __syncthreads();            // reads of scr done before reuse

    // ---- fused count for the NEW center (next iteration's gate) ----
    if (doCount) {
        int cnt = 0;
        #pragma unroll 4
        for (int p = t; p < N_PTS; p += TPB_SEG) {
            float2 xy = g_xy[p];
            float dx = xy.x - ccx, dy = xy.y - ccy;
            float sp2 = __fadd_rn(__fmul_rn(dx, dx), __fmul_rn(dy, dy));
            cnt += (sp2 <= Y0);
        }
        #pragma unroll
        for (int o = 16; o > 0; o >>= 1)
            cnt += __shfl_down_sync(0xffffffffu, cnt, o);
        int* iscr = (int*)scr;
        if ((t & 31) == 0) iscr[t >> 5] = cnt;
        __syncthreads();
        if (t == 0) {
            int s = 0;
            #pragma unroll
            for (int w = 0; w < TPB_SEG / 32; w++) s += iscr[w];
            g_counts[cl] = s;
        }
    }

    // ---- convergence (last block, exact same tree order as before) ----
    __threadfence();
    __syncthreads();
    int* iscr = (int*)scr;
    if (t == 0) {
        int old = atomicAdd(&g_ticket2, 1);
        iscr[16] = (old == NUM - 1);
    }
    __syncthreads();
    if (iscr[16]) {
        float* red = scr + 64;
        if (t < NUM) red[t] = g_dsq[t];
        __syncthreads();
        #pragma unroll
        for (int s2 = 64; s2 > 0; s2 >>= 1) {
            if (t < s2) red[t] += red[t + s2];
            __syncthreads();
        }
        if (t == 0) {
            if (red[0] < THRESH2) g_converged = 1;
            g_ticket2 = 0;
        }
    }
}

// ------------------------------------------------------------------
// Output: [ labels as float (N) | centers (NUM*FD) ], float32
__global__ void __launch_bounds__(256) outputKernel(float* __restrict__ out, int out_size) {
    int idx = blockIdx.x * 256 + threadIdx.x;
    if (idx < N_PTS && idx < out_size)
        out[idx] = (float)g_labels[idx];
    if (idx < NUM * FD && (N_PTS + idx) < out_size)
        out[N_PTS + idx] = g_centers[idx];
}

// ------------------------------------------------------------------
extern "C" void kernel_launch(void* const* d_in, const int* in_sizes, int n_in,
                              void* d_out, int out_size) {
    const float* data    = (const float*)d_in[0];
    const float* centers = (const float*)d_in[1];

    // Y0 = largest f32 y with sqrt_rn(y) <= r, r = 0.32f.
    float  r  = 0.32f;
    double m  = 0.5 * ((double)r + (double)nextafterf(r, 2.0f));
    double m2 = m * m;
    float  Y0 = (float)m2;
    if ((double)Y0 >= m2) Y0 = nextafterf(Y0, 0.0f);

    initKernel<<<1, 1024>>>(centers);
    packKernel<<<NBLK, 256>>>(data);
    countKernel<<<NBLK, 256>>>(Y0);          // iteration-0 gate only
    for (int it = 0; it < MAXIT; it++) {
        assignKernel<<<NBLK, 256>>>(data, Y0);
        scanKernel<<<NUM, 128>>>();
        scatterKernel<<<NBLK, 256>>>();
        segsumKernel<<<NUM, TPB_SEG>>>(data, Y0, (it < MAXIT - 1) ? 1 : 0);
    }
    outputKernel<<<NBLK, 256>>>((float*)d_out, out_size);
}

// round 9
// speedup vs baseline: 1.1524x; 1.1524x over previous
#include <cuda_runtime.h>
#include <math.h>

#define N_PTS   524288
#define FD      8
#define NUM     128
#define MAXIT   5
#define EPSF    1e-6f
#define THRESH2 1e-8f        /* (1e-4)^2 */
#define NBLK    (N_PTS / 256)   /* 2048 */
#define TPB_SEG 256
#define TILE    768             /* 2*768*8*4 = 49152 B static smem (max) */

// ---- device scratch (no allocations allowed) ----
__device__ float  g_centers[NUM * FD];
__device__ int    g_counts[NUM];
__device__ float  g_dsq[NUM];
__device__ int    g_labels[N_PTS];
__device__ int    g_converged;
__device__ int    g_ticket1;
__device__ int    g_ticket2;
__device__ __align__(16) float2 g_xy[N_PTS];  // packed first-2 coords (4 MB)
// counting-sort scratch
__device__ int    g_blockhist[NBLK * NUM];
__device__ int    g_blockpre[NBLK * NUM];
__device__ int    g_base[NUM];
__device__ int    g_total[NUM];
__device__ int    g_idx[N_PTS];

// ------------------------------------------------------------------
__global__ void initKernel(const float* __restrict__ centers_in) {
    int t = threadIdx.x;                    // 1024 threads, 1 block
    g_centers[t] = centers_in[t];           // NUM*FD == 1024
    if (t < NUM) g_counts[t] = 0;
    if (t == 0) { g_converged = 0; g_ticket1 = 0; g_ticket2 = 0; }
}

// Pack xy coords once (coords never change).
__global__ void __launch_bounds__(256) packKernel(const float* __restrict__ data) {
    int idx = blockIdx.x * 256 + threadIdx.x;
    g_xy[idx] = *(const float2*)(data + (size_t)idx * FD);
}

// ------------------------------------------------------------------
// Per-center in-radius counts (spatial gate). Exact replication of
// in_r = sqrt_rn(dx*dx+dy*dy) <= r via sp2 <= Y0. Register-accumulated:
// lane ii owns centers ii, ii+32, ii+64, ii+96 (integer order-free).
// g_counts is zeroed by initKernel (iter 0) / segsumKernel (iters 1+).
__global__ void __launch_bounds__(256) countKernel(float Y0) {
    if (g_converged) return;
    __shared__ float2 c2[NUM];
    __shared__ int    scnt[NUM];
    int t = threadIdx.x;
    if (t < NUM) {
        c2[t] = make_float2(g_centers[t * FD], g_centers[t * FD + 1]);
        scnt[t] = 0;
    }
    __syncthreads();

    int idx  = blockIdx.x * 256 + t;
    float2 p = g_xy[idx];
    int lane = t & 31;

    int cnt0 = 0, cnt1 = 0, cnt2 = 0, cnt3 = 0;
    #pragma unroll 4
    for (int ii = 0; ii < 32; ii++) {
        bool mine = (lane == ii);
        #pragma unroll
        for (int q = 0; q < 4; q++) {
            int i = q * 32 + ii;
            float dx = p.x - c2[i].x;
            float dy = p.y - c2[i].y;
            float sp2 = __fadd_rn(__fmul_rn(dx, dx), __fmul_rn(dy, dy));
            unsigned m = __ballot_sync(0xffffffffu, sp2 <= Y0);
            int pc = __popc(m);
            if (mine) {
                if (q == 0) cnt0 += pc;
                if (q == 1) cnt1 += pc;
                if (q == 2) cnt2 += pc;
                if (q == 3) cnt3 += pc;
            }
        }
    }
    atomicAdd(&scnt[lane],      cnt0);
    atomicAdd(&scnt[lane + 32], cnt1);
    atomicAdd(&scnt[lane + 64], cnt2);
    atomicAdd(&scnt[lane + 96], cnt3);
    __syncthreads();
    if (t < NUM) atomicAdd(&g_counts[t], scnt[t]);
}

// ------------------------------------------------------------------
// Assignment: faithful reference fp arithmetic, + per-block label histogram.
// Early warp-uniform break once all lanes are poisoned (provable no-op).
__global__ void __launch_bounds__(256) assignKernel(const float* __restrict__ data,
                                                    float Y0) {
    if (g_converged) return;
    __shared__ float4 sc[NUM * 2];
    __shared__ int    shist[NUM];
    int t = threadIdx.x;

    {   // centers with "enough" gate baked into coord 0
        float4 v = ((const float4*)g_centers)[t];
        if ((t & 1) == 0) {
            if (g_counts[t >> 1] <= 1) v.x += 1e9f;
        }
        sc[t] = v;
    }
    if (t < NUM) shist[t] = 0;
    __syncthreads();

    int idx = blockIdx.x * 256 + t;
    float4 p0 = ((const float4*)data)[2 * idx];
    float4 p1 = ((const float4*)data)[2 * idx + 1];

    float dval = 1000.0f;
    int   label = -1;

    for (int i = 0; i < NUM; i++) {
        float4 c0 = sc[2 * i];
        float dx0 = p0.x - c0.x;
        float dx1 = p0.y - c0.y;
        float sp2 = __fadd_rn(__fmul_rn(dx0, dx0), __fmul_rn(dx1, dx1));
        bool need = (sp2 <= Y0) && (dval > 0.0f);
        if (__any_sync(0xffffffffu, need)) {
            float4 c1 = sc[2 * i + 1];
            float t0 = __fadd_rn(dx0, EPSF);
            float t1 = __fadd_rn(dx1, EPSF);
            float t2 = __fadd_rn(p0.z - c0.z, EPSF);
            float t3 = __fadd_rn(p0.w - c0.w, EPSF);
            float t4 = __fadd_rn(p1.x - c1.x, EPSF);
            float t5 = __fadd_rn(p1.y - c1.y, EPSF);
            float t6 = __fadd_rn(p1.z - c1.z, EPSF);
            float t7 = __fadd_rn(p1.w - c1.w, EPSF);
            float s = __fmul_rn(t0, t0);
            s = __fadd_rn(s, __fmul_rn(t1, t1));
            s = __fadd_rn(s, __fmul_rn(t2, t2));
            s = __fadd_rn(s, __fmul_rn(t3, t3));
            s = __fadd_rn(s, __fmul_rn(t4, t4));
            s = __fadd_rn(s, __fmul_rn(t5, t5));
            s = __fadd_rn(s, __fmul_rn(t6, t6));
            s = __fadd_rn(s, __fmul_rn(t7, t7));
            float D = __fsqrt_rn(s);
            if (need) {
                if (D < dval) { label = i; dval = D; }
                else          { dval = 0.0f; }
            }
        } else if (__all_sync(0xffffffffu, dval == 0.0f)) {
            break;
        }
    }

    g_labels[idx] = label;
    if (label >= 0) atomicAdd(&shist[label], 1);
    __syncthreads();
    if (t < NUM) g_blockhist[blockIdx.x * NUM + t] = shist[t];
}

// ------------------------------------------------------------------
// Per-cluster exclusive prefix over the 2048 block histograms, with the
// cross-cluster base scan fused into the last-arriving block (ticket).
__global__ void __launch_bounds__(128) scanKernel() {
    if (g_converged) return;
    __shared__ int wsum[4];
    __shared__ int sh[NUM];
    __shared__ int lastFlag;
    int cl   = blockIdx.x;
    int t    = threadIdx.x;             // 0..127
    int lane = t & 31, wid = t >> 5;
    const int PER = NBLK / 128;         // 16

    int v[PER];
    int s = 0;
    #pragma unroll
    for (int j = 0; j < PER; j++) {
        v[j] = g_blockhist[(t * PER + j) * NUM + cl];
        s += v[j];
    }

    int inc = s;
    #pragma unroll
    for (int o = 1; o < 32; o <<= 1) {
        int x = __shfl_up_sync(0xffffffffu, inc, o);
        if (lane >= o) inc += x;
    }
    if (lane == 31) wsum[wid] = inc;
    __syncthreads();
    int woff = 0;
    #pragma unroll
    for (int w = 0; w < 4; w++)
        if (w < wid) woff += wsum[w];

    if (t == 127) g_total[cl] = woff + inc;

    int run = woff + (inc - s);
    #pragma unroll
    for (int j = 0; j < PER; j++) {
        g_blockpre[(t * PER + j) * NUM + cl] = run;
        run += v[j];
    }

    // ---- fused base scan (last block via ticket) ----
    __threadfence();
    __syncthreads();
    if (t == 0) {
        int old = atomicAdd(&g_ticket1, 1);
        lastFlag = (old == NUM - 1);
    }
    __syncthreads();
    if (lastFlag) {
        int tv = g_total[t];
        sh[t] = tv;
        __syncthreads();
        #pragma unroll
        for (int o = 1; o < NUM; o <<= 1) {
            int x = (t >= o) ? sh[t - o] : 0;
            __syncthreads();
            sh[t] += x;
            __syncthreads();
        }
        g_base[t] = sh[t] - tv;
        if (t == 0) g_ticket1 = 0;
    }
}

// ------------------------------------------------------------------
// Stable scatter: point index -> g_idx, ascending index within each cluster.
__global__ void __launch_bounds__(256) scatterKernel() {
    if (g_converged) return;
    __shared__ int whist[8][NUM];
    int t    = threadIdx.x;
    int wid  = t >> 5;
    int lane = t & 31;

    #pragma unroll
    for (int j = t; j < 8 * NUM; j += 256) ((int*)whist)[j] = 0;
    __syncthreads();

    int idx = blockIdx.x * 256 + t;
    int lab = g_labels[idx];

    unsigned mask = __match_any_sync(0xffffffffu, lab);
    int rank   = __popc(mask & ((1u << lane) - 1u));
    int leader = __ffs(mask) - 1;
    if (lab >= 0 && lane == leader) whist[wid][lab] = __popc(mask);
    __syncthreads();

    if (t < NUM) {
        int run = 0;
        #pragma unroll
        for (int w = 0; w < 8; w++) {
            int v = whist[w][t];
            whist[w][t] = run;
            run += v;
        }
    }
    __syncthreads();

    if (lab >= 0) {
        int pos = g_base[lab] + g_blockpre[blockIdx.x * NUM + lab]
                + whist[wid][lab] + rank;
        g_idx[pos] = idx;
    }
}

// ------------------------------------------------------------------
// Exact ascending-order segment sums (tile-pipelined) FUSED with the
// per-cluster center update, the per-cluster count reset, and the
// last-block convergence check.
__global__ void __launch_bounds__(TPB_SEG) segsumKernel(const float* __restrict__ data) {
    if (g_converged) return;
    __shared__ float buf[2][TILE][FD];     // 49152 B; tail phases reuse it
    int cl = blockIdx.x;
    int t  = threadIdx.x;
    int start = g_base[cl];
    int n     = g_total[cl];
    int ntiles = (n + TILE - 1) / TILE;

    #define LOAD_TILE(g, s)                                              \
        do {                                                             \
            _Pragma("unroll")                                            \
            for (int h = 0; h < TILE / TPB_SEG; h++) {                   \
                int p = (g) * TILE + h * TPB_SEG + t;                    \
                if (p < n) {                                             \
                    int id = g_idx[start + p];                           \
                    float4 a = ((const float4*)data)[2 * id];            \
                    float4 b = ((const float4*)data)[2 * id + 1];        \
                    float* dst = buf[s][h * TPB_SEG + t];                \
                    ((float4*)dst)[0] = a;                               \
                    ((float4*)dst)[1] = b;                               \
                }                                                        \
            }                                                            \
        } while (0)

    if (ntiles > 0) LOAD_TILE(0, 0);
    __syncthreads();

    float acc = 0.0f;
    for (int g = 0; g < ntiles; g++) {
        int s = g & 1;
        if (g + 1 < ntiles) LOAD_TILE(g + 1, s ^ 1);
        int m = min(n - g * TILE, TILE);
        if (t < FD) {
            #pragma unroll 16
            for (int k = 0; k < m; k++)
                acc = __fadd_rn(acc, buf[s][k][t]);
        }
        __syncthreads();
    }
    #undef LOAD_TILE

    // ---- fused center update (fp ops identical to reference order) ----
    float* scr = &buf[0][0][0];
    if (t < FD) {
        float oldc = g_centers[cl * FD + t];
        float cntf = (float)n;
        float den  = fmaxf(cntf, 1.0f);
        float mval = __fdiv_rn(acc, den);
        float nc   = (cntf > 0.0f) ? mval : oldc;
        float d    = nc - oldc;
        g_centers[cl * FD + t] = nc;
        scr[t] = d;
    }
    if (t == 8) g_counts[cl] = 0;   // reset this cluster's gate accumulator
    __syncthreads();
    if (t == 0) {
        float dsq = 0.0f;
        #pragma unroll
        for (int k = 0; k < FD; k++)
            dsq = __fadd_rn(dsq, __fmul_rn(scr[k], scr[k]));
        g_dsq[cl] = dsq;
    }

    // ---- convergence (last block via ticket, exact tree order) ----
    __threadfence();
    __syncthreads();
    int* iscr = (int*)scr;
    if (t == 0) {
        int old = atomicAdd(&g_ticket2, 1);
        iscr[16] = (old == NUM - 1);
    }
    __syncthreads();
    if (iscr[16]) {
        float* red = scr + 64;
        if (t < NUM) red[t] = g_dsq[t];
        __syncthreads();
        #pragma unroll
        for (int s2 = 64; s2 > 0; s2 >>= 1) {
            if (t < s2) red[t] += red[t + s2];
            __syncthreads();
        }
        if (t == 0) {
            if (red[0] < THRESH2) g_converged = 1;
            g_ticket2 = 0;
        }
    }
}

// ------------------------------------------------------------------
// Output: [ labels as float (N) | centers (NUM*FD) ], float32
__global__ void __launch_bounds__(256) outputKernel(float* __restrict__ out, int out_size) {
    int idx = blockIdx.x * 256 + threadIdx.x;
    if (idx < N_PTS && idx < out_size)
        out[idx] = (float)g_labels[idx];
    if (idx < NUM * FD && (N_PTS + idx) < out_size)
        out[N_PTS + idx] = g_centers[idx];
}

// ------------------------------------------------------------------
extern "C" void kernel_launch(void* const* d_in, const int* in_sizes, int n_in,
                              void* d_out, int out_size) {
    const float* data    = (const float*)d_in[0];
    const float* centers = (const float*)d_in[1];

    // Y0 = largest f32 y with sqrt_rn(y) <= r, r = 0.32f.
    float  r  = 0.32f;
    double m  = 0.5 * ((double)r + (double)nextafterf(r, 2.0f));
    double m2 = m * m;
    float  Y0 = (float)m2;
    if ((double)Y0 >= m2) Y0 = nextafterf(Y0, 0.0f);

    initKernel<<<1, 1024>>>(centers);
    packKernel<<<NBLK, 256>>>(data);
    for (int it = 0; it < MAXIT; it++) {
        countKernel<<<NBLK, 256>>>(Y0);
        assignKernel<<<NBLK, 256>>>(data, Y0);
        scanKernel<<<NUM, 128>>>();             // + fused base scan
        scatterKernel<<<NBLK, 256>>>();
        segsumKernel<<<NUM, TPB_SEG>>>(data);   // + fused update/convergence/reset
    }
    outputKernel<<<NBLK, 256>>>((float*)d_out, out_size);
}